// round 9
// baseline (speedup 1.0000x reference)
#include <cuda_runtime.h>
#include <math.h>

#define NN 25000
#define NE 400000
#define ND 100
#define EDICT 16

// ---------------- device scratch (zero at load; k3 restores every replay) ----------------
__device__ float4 g_tabT[ND * 32];        // P table: [d][f] -> 4 heads (51.2KB)
__device__ float4 g_s1[ND];
__device__ float4 g_s2[ND];
__device__ float4 g_s3[EDICT];
__device__ float4 g_lnedge[EDICT * 32];   // 16 LN'd edge rows (8KB)
__device__ int    g_deg[NN];
__device__ float4 g_Wmat[NN * ND];        // [t][d] -> per-head sum of exp (40MB, L2-resident)

// edge-out partition (by edge index)
#define E_SPLIT1 160000
#define E_SPLIT2 280000

// ---------------- shared GEMV helper: one dict row, 256 thr, K-split 2 x 8 chains ----------------
__device__ __forceinline__ float dict_gemv(const float* __restrict__ emb,
                                           const float* __restrict__ W,
                                           const float* __restrict__ bias,
                                           float* sh, float* part,
                                           int col, int half)
{
    if (half == 0) sh[col] = emb[col];
    __syncthreads();
    int k0 = half * 64;
    float c0 = 0.f, c1 = 0.f, c2 = 0.f, c3 = 0.f;
    float c4 = 0.f, c5 = 0.f, c6 = 0.f, c7 = 0.f;
#pragma unroll
    for (int i = 0; i < 64; i += 8) {
        c0 += sh[k0 + i]     * W[(k0 + i) * 128 + col];
        c1 += sh[k0 + i + 1] * W[(k0 + i + 1) * 128 + col];
        c2 += sh[k0 + i + 2] * W[(k0 + i + 2) * 128 + col];
        c3 += sh[k0 + i + 3] * W[(k0 + i + 3) * 128 + col];
        c4 += sh[k0 + i + 4] * W[(k0 + i + 4) * 128 + col];
        c5 += sh[k0 + i + 5] * W[(k0 + i + 5) * 128 + col];
        c6 += sh[k0 + i + 6] * W[(k0 + i + 6) * 128 + col];
        c7 += sh[k0 + i + 7] * W[(k0 + i + 7) * 128 + col];
    }
    float partial = ((c0 + c1) + (c2 + c3)) + ((c4 + c5) + (c6 + c7));
    if (half == 1) part[col] = partial;
    __syncthreads();
    if (half == 1) return 0.f;   // caller returns early for half==1
    return partial + part[col] + bias[col];
}

// ==================== K0: edge dict tables (16 blocks) ====================
__global__ void __launch_bounds__(256) k0_edgetab(
    const float* __restrict__ edge_emb,
    const float* __restrict__ W_e, const float* __restrict__ b_e,
    const float* __restrict__ a_w,
    const float* __restrict__ gamma, const float* __restrict__ beta)
{
    __shared__ float sh[128];
    __shared__ float part[128];
    __shared__ float red[8];
    int b = blockIdx.x;
    int tid = threadIdx.x;
    int col = tid & 127;
    int half = tid >> 7;

    float acc = dict_gemv(edge_emb + b * 128, W_e, b_e, sh, part, col, half);
    if (half == 1) return;

    int h = col >> 5;
    int f = col & 31;
    float u = acc * a_w[64 + f];
    float s = acc;
#pragma unroll
    for (int o = 16; o; o >>= 1) {
        u += __shfl_xor_sync(0xFFFFFFFFu, u, o);
        s += __shfl_xor_sync(0xFFFFFFFFu, s, o);
    }
    if (f == 0) {
        ((float*)&g_s3[b])[h] = u;
        red[h] = s;
    }
    __syncthreads();
    float mu = (red[0] + red[1] + red[2] + red[3]) * (1.f / 128.f);
    float dd = acc - mu;
    float sq = dd * dd;
#pragma unroll
    for (int o = 16; o; o >>= 1) sq += __shfl_xor_sync(0xFFFFFFFFu, sq, o);
    if (f == 0) red[4 + h] = sq;
    __syncthreads();
    float var = (red[4] + red[5] + red[6] + red[7]) * (1.f / 128.f);
    ((float*)g_lnedge)[b * 128 + col] = dd * rsqrtf(var + 1e-5f) * gamma[col] + beta[col];
}

// ---------------- strided edge-out streamer (4-way MLP, evict-first) ----------------
__device__ __forceinline__ void eout_stream(const int* __restrict__ ef,
                                            float4* __restrict__ out_edge,
                                            int start, int end, int gw, int l, int stride)
{
    int e = start + gw;
    for (; e + 3 * stride < end; e += 4 * stride) {
        int k0 = __ldg(&ef[e]);
        int k1 = __ldg(&ef[e + stride]);
        int k2 = __ldg(&ef[e + 2 * stride]);
        int k3 = __ldg(&ef[e + 3 * stride]);
        float4 v0 = g_lnedge[(k0 << 5) + l];
        float4 v1 = g_lnedge[(k1 << 5) + l];
        float4 v2 = g_lnedge[(k2 << 5) + l];
        float4 v3 = g_lnedge[(k3 << 5) + l];
        __stcs(&out_edge[(size_t)e * 32 + l], v0);
        __stcs(&out_edge[(size_t)(e + stride) * 32 + l], v1);
        __stcs(&out_edge[(size_t)(e + 2 * stride) * 32 + l], v2);
        __stcs(&out_edge[(size_t)(e + 3 * stride) * 32 + l], v3);
    }
    for (; e < end; e += stride) {
        int k = __ldg(&ef[e]);
        __stcs(&out_edge[(size_t)e * 32 + l], g_lnedge[(k << 5) + l]);
    }
}

// ==================== K1: node dict tables (100) + eout [0, E_SPLIT1) ====================
#define G1 1184
#define EO1_BLKS (G1 - ND)     // 1084

__global__ void __launch_bounds__(256) k1_nodetab(
    const float* __restrict__ node_emb,
    const float* __restrict__ W_t, const float* __restrict__ b_t,
    const float* __restrict__ a_w,
    const int* __restrict__ ef, float4* __restrict__ out_edge)
{
    int bid = blockIdx.x;
    int tid = threadIdx.x;

    if (bid >= ND) {
        int eb = bid - ND;
        int l = tid & 31;
        int gw = eb * 8 + (tid >> 5);
        eout_stream(ef, out_edge, 0, E_SPLIT1, gw, l, EO1_BLKS * 8);
        return;
    }

    __shared__ float sh[128];
    __shared__ float part[128];
    int col = tid & 127;
    int half = tid >> 7;

    float acc = dict_gemv(node_emb + bid * 128, W_t, b_t, sh, part, col, half);
    if (half == 1) return;

    int h = col >> 5;
    int f = col & 31;
    ((float*)&g_tabT[bid * 32 + f])[h] = acc;
    float u = acc * a_w[f];
    float v = acc * a_w[32 + f];
#pragma unroll
    for (int o = 16; o; o >>= 1) {
        u += __shfl_xor_sync(0xFFFFFFFFu, u, o);
        v += __shfl_xor_sync(0xFFFFFFFFu, v, o);
    }
    if (f == 0) {
        ((float*)&g_s1[bid])[h] = u;
        ((float*)&g_s2[bid])[h] = v;
    }
}

// ==================== K2: edge atomics (1/3) + eout [E_SPLIT1, E_SPLIT2) (2/3) ====================
#define G2 1184
#define NCMP2 395
#define EO2_BLKS (G2 - NCMP2 + 1)   // blocks with bid%3!=0: 789

__global__ void __launch_bounds__(256) k2_edges(
    const int* __restrict__ nf, const int* __restrict__ ef,
    const int* __restrict__ ei, const float* __restrict__ a_b,
    float4* __restrict__ out_edge)
{
    int bid = blockIdx.x;
    int tid = threadIdx.x;

    if (bid % 3 != 0) {
        int eb = bid - bid / 3 - 1;   // 0..788
        int l = tid & 31;
        int gw = eb * 8 + (tid >> 5);
        eout_stream(ef, out_edge, E_SPLIT1, E_SPLIT2, gw, l, 789 * 8);
        return;
    }

    int cb = bid / 3;
    float ab = __ldg(a_b);
    for (int e = cb * 256 + tid; e < NE; e += NCMP2 * 256) {
        int s = __ldg(&ei[e]);
        int t = __ldg(&ei[NE + e]);
        int k = __ldg(&ef[e]);
        int ds = __ldg(&nf[s]);
        int dt = __ldg(&nf[t]);
        float4 z1 = g_s1[dt];
        float4 z2 = g_s2[ds];
        float4 z3 = g_s3[k];

        float zx = z1.x + z2.x + z3.x + ab;
        float zy = z1.y + z2.y + z3.y + ab;
        float zz = z1.z + z2.z + z3.z + ab;
        float zw = z1.w + z2.w + z3.w + ab;
        zx = zx >= 0.f ? zx : 0.2f * zx;
        zy = zy >= 0.f ? zy : 0.2f * zy;
        zz = zz >= 0.f ? zz : 0.2f * zz;
        zw = zw >= 0.f ? zw : 0.2f * zw;
        float ex = __expf(zx), ey = __expf(zy), ez = __expf(zz), ew = __expf(zw);

        float4* wp = &g_Wmat[t * ND + ds];
        asm volatile("red.global.add.v4.f32 [%0], {%1,%2,%3,%4};"
                     :: "l"(wp), "f"(ex), "f"(ey), "f"(ez), "f"(ew) : "memory");
        atomicAdd(&g_deg[t], 1);
    }
}

// ==================== K3: node GEMM+LN+restore (1/3) + eout [E_SPLIT2, NE) (2/3) ====================
#define NPB3 16
#define NT3 ((NN + NPB3 - 1) / NPB3)   // 1563
#define G3 1184
#define NCMP3 395

__global__ void __launch_bounds__(256) k3_nodes(
    const int* __restrict__ nf, const int* __restrict__ ef,
    const float* __restrict__ gamma, const float* __restrict__ beta,
    float* __restrict__ out_node, float4* __restrict__ out_edge)
{
    int bid = blockIdx.x;
    int tid = threadIdx.x;
    int l = tid & 31;

    if (bid % 3 != 0) {
        int eb = bid - bid / 3 - 1;
        int gw = eb * 8 + (tid >> 5);
        eout_stream(ef, out_edge, E_SPLIT2, NE, gw, l, 789 * 8);
        return;
    }

    __shared__ float4 Ws[NPB3 * ND];   // 25.6KB
    int cb = bid / 3;
    int w = tid >> 5;
    const float4 z4 = make_float4(0.f, 0.f, 0.f, 0.f);

    float gl0 = gamma[l],      bl0 = beta[l];
    float gl1 = gamma[32 + l], bl1 = beta[32 + l];
    float gl2 = gamma[64 + l], bl2 = beta[64 + l];
    float gl3 = gamma[96 + l], bl3 = beta[96 + l];

    for (int tile = cb; tile < NT3; tile += NCMP3) {
        int base = tile * NPB3;
        __syncthreads();   // Ws reuse guard
        for (int i = tid; i < NPB3 * ND; i += 256) {
            int t = base + i / ND;
            Ws[i] = (t < NN) ? __ldcs(&g_Wmat[t * ND + (i % ND)]) : z4;
        }
        __syncthreads();
        // restore zeros (dense batched stores, L2-resident)
        for (int i = tid; i < NPB3 * ND; i += 256) {
            int t = base + i / ND;
            if (t < NN) g_Wmat[t * ND + (i % ND)] = z4;
        }

        const float4* Wa = &Ws[(2 * w + 0) * ND];
        const float4* Wb = &Ws[(2 * w + 1) * ND];
        float4 acc0 = z4, acc1 = z4, ss0 = z4, ss1 = z4;

#pragma unroll 4
        for (int d = 0; d < ND; d++) {
            float4 wa = Wa[d], wb = Wb[d];
            if (wa.x + wb.x > 0.f) {
                float4 p = __ldg(&g_tabT[(d << 5) + l]);
                acc0.x += wa.x * p.x; acc0.y += wa.y * p.y; acc0.z += wa.z * p.z; acc0.w += wa.w * p.w;
                acc1.x += wb.x * p.x; acc1.y += wb.y * p.y; acc1.z += wb.z * p.z; acc1.w += wb.w * p.w;
                ss0.x += wa.x; ss0.y += wa.y; ss0.z += wa.z; ss0.w += wa.w;
                ss1.x += wb.x; ss1.y += wb.y; ss1.z += wb.z; ss1.w += wb.w;
            }
        }

#pragma unroll
        for (int n = 0; n < 2; n++) {
            int t = base + 2 * w + n;
            if (t >= NN) break;
            float4 a  = (n == 0) ? acc0 : acc1;
            float4 ss = (n == 0) ? ss0  : ss1;
            float r0 = ss.x > 0.f ? 1.f / ss.x : 0.f;
            float r1 = ss.y > 0.f ? 1.f / ss.y : 0.f;
            float r2 = ss.z > 0.f ? 1.f / ss.z : 0.f;
            float r3 = ss.w > 0.f ? 1.f / ss.w : 0.f;
            float dg = (float)__ldg(&g_deg[t]);
            if (l == 0) g_deg[t] = 0;                       // restore
            float4 p = __ldg(&g_tabT[(__ldg(&nf[t]) << 5) + l]);

            float v0 = a.x * r0 + dg * p.x;
            float v1 = a.y * r1 + dg * p.y;
            float v2 = a.z * r2 + dg * p.z;
            float v3 = a.w * r3 + dg * p.w;

            float s = v0 + v1 + v2 + v3;
#pragma unroll
            for (int o = 16; o; o >>= 1) s += __shfl_xor_sync(0xFFFFFFFFu, s, o);
            float mu = s * (1.f / 128.f);
            float d0 = v0 - mu, d1 = v1 - mu, d2 = v2 - mu, d3 = v3 - mu;
            float sq = d0 * d0 + d1 * d1 + d2 * d2 + d3 * d3;
#pragma unroll
            for (int o = 16; o; o >>= 1) sq += __shfl_xor_sync(0xFFFFFFFFu, sq, o);
            float rs = rsqrtf(sq * (1.f / 128.f) + 1e-5f);

            float* o0 = out_node + (size_t)t * 128;
            __stcs(&o0[l],      d0 * rs * gl0 + bl0);
            __stcs(&o0[32 + l], d1 * rs * gl1 + bl1);
            __stcs(&o0[64 + l], d2 * rs * gl2 + bl2);
            __stcs(&o0[96 + l], d3 * rs * gl3 + bl3);
        }
    }
}

// ==================== launch ====================
extern "C" void kernel_launch(void* const* d_in, const int* in_sizes, int n_in,
                              void* d_out, int out_size) {
    const int*   nf       = (const int*)d_in[0];
    const int*   ef       = (const int*)d_in[1];
    const int*   ei       = (const int*)d_in[2];
    const float* node_emb = (const float*)d_in[3];
    const float* edge_emb = (const float*)d_in[4];
    const float* W_t      = (const float*)d_in[5];
    const float* b_t      = (const float*)d_in[6];
    const float* W_e      = (const float*)d_in[7];
    const float* b_e      = (const float*)d_in[8];
    const float* a_w      = (const float*)d_in[9];
    const float* a_b      = (const float*)d_in[10];
    const float* gamma    = (const float*)d_in[11];
    const float* beta     = (const float*)d_in[12];

    float* out_node = (float*)d_out;                                  // [25000,128]
    float4* out_edge = (float4*)((float*)d_out + (size_t)NN * 128);   // [400000,128]

    k0_edgetab<<<EDICT, 256>>>(edge_emb, W_e, b_e, a_w, gamma, beta);
    k1_nodetab<<<G1, 256>>>(node_emb, W_t, b_t, a_w, ef, out_edge);
    k2_edges<<<G2, 256>>>(nf, ef, ei, a_b, out_edge);
    k3_nodes<<<G3, 256>>>(nf, ef, gamma, beta, out_node, out_edge);
}

// round 10
// speedup vs baseline: 1.2221x; 1.2221x over previous
#include <cuda_runtime.h>
#include <math.h>

#define NN 25000
#define NE 400000
#define ND 100
#define EDICT 16

#define E_SPLIT 120000            // k1 streams [0, E_SPLIT); k2 fuses [E_SPLIT, NE)

// ---------------- device scratch (zeroed at load; k3 restores every replay) ----------------
__device__ float4 g_tabT[ND * 32];        // P table: [d][f] -> 4 heads (51.2KB)
__device__ float4 g_s1[ND];
__device__ float4 g_s2[ND];
__device__ float4 g_s3[EDICT];
__device__ float4 g_lnedge[EDICT * 32];   // 16 LN'd edge rows (8KB)
__device__ int    g_deg[NN];
__device__ float4 g_Wmat[NN * ND];        // [t][d] -> per-head sum of exp (40MB)

// ---------------- shared GEMV helper: one dict row, 256 thr, K-split, 8 chains ----------------
__device__ __forceinline__ float dict_gemv(const float* __restrict__ emb,
                                           const float* __restrict__ W,
                                           const float* __restrict__ bias,
                                           float* sh, float* part,
                                           int col, int half)
{
    if (half == 0) sh[col] = emb[col];
    __syncthreads();
    int k0 = half * 64;
    float c0 = 0.f, c1 = 0.f, c2 = 0.f, c3 = 0.f;
    float c4 = 0.f, c5 = 0.f, c6 = 0.f, c7 = 0.f;
#pragma unroll
    for (int i = 0; i < 64; i += 8) {
        c0 += sh[k0 + i]     * W[(k0 + i) * 128 + col];
        c1 += sh[k0 + i + 1] * W[(k0 + i + 1) * 128 + col];
        c2 += sh[k0 + i + 2] * W[(k0 + i + 2) * 128 + col];
        c3 += sh[k0 + i + 3] * W[(k0 + i + 3) * 128 + col];
        c4 += sh[k0 + i + 4] * W[(k0 + i + 4) * 128 + col];
        c5 += sh[k0 + i + 5] * W[(k0 + i + 5) * 128 + col];
        c6 += sh[k0 + i + 6] * W[(k0 + i + 6) * 128 + col];
        c7 += sh[k0 + i + 7] * W[(k0 + i + 7) * 128 + col];
    }
    float partial = ((c0 + c1) + (c2 + c3)) + ((c4 + c5) + (c6 + c7));
    if (half == 1) part[col] = partial;
    __syncthreads();
    if (half == 1) return 0.f;
    return partial + part[col] + bias[col];
}

// ==================== K0: edge dict tables (16 blocks) ====================
__global__ void __launch_bounds__(256) k0_edgetab(
    const float* __restrict__ edge_emb,
    const float* __restrict__ W_e, const float* __restrict__ b_e,
    const float* __restrict__ a_w,
    const float* __restrict__ gamma, const float* __restrict__ beta)
{
    __shared__ float sh[128];
    __shared__ float part[128];
    __shared__ float red[8];
    int b = blockIdx.x;
    int tid = threadIdx.x;
    int col = tid & 127;
    int half = tid >> 7;

    float acc = dict_gemv(edge_emb + b * 128, W_e, b_e, sh, part, col, half);
    if (half == 1) return;

    int h = col >> 5;
    int f = col & 31;
    float u = acc * a_w[64 + f];
    float s = acc;
#pragma unroll
    for (int o = 16; o; o >>= 1) {
        u += __shfl_xor_sync(0xFFFFFFFFu, u, o);
        s += __shfl_xor_sync(0xFFFFFFFFu, s, o);
    }
    if (f == 0) {
        ((float*)&g_s3[b])[h] = u;
        red[h] = s;
    }
    __syncthreads();
    float mu = (red[0] + red[1] + red[2] + red[3]) * (1.f / 128.f);
    float dd = acc - mu;
    float sq = dd * dd;
#pragma unroll
    for (int o = 16; o; o >>= 1) sq += __shfl_xor_sync(0xFFFFFFFFu, sq, o);
    if (f == 0) red[4 + h] = sq;
    __syncthreads();
    float var = (red[4] + red[5] + red[6] + red[7]) * (1.f / 128.f);
    ((float*)g_lnedge)[b * 128 + col] = dd * rsqrtf(var + 1e-5f) * gamma[col] + beta[col];
}

// ---------------- strided edge-out streamer (4-way MLP, evict-first) ----------------
__device__ __forceinline__ void eout_stream(const int* __restrict__ ef,
                                            float4* __restrict__ out_edge,
                                            int start, int end, int gw, int l, int stride)
{
    int e = start + gw;
    for (; e + 3 * stride < end; e += 4 * stride) {
        int k0 = __ldg(&ef[e]);
        int k1 = __ldg(&ef[e + stride]);
        int k2 = __ldg(&ef[e + 2 * stride]);
        int k3 = __ldg(&ef[e + 3 * stride]);
        float4 v0 = g_lnedge[(k0 << 5) + l];
        float4 v1 = g_lnedge[(k1 << 5) + l];
        float4 v2 = g_lnedge[(k2 << 5) + l];
        float4 v3 = g_lnedge[(k3 << 5) + l];
        __stcs(&out_edge[(size_t)e * 32 + l], v0);
        __stcs(&out_edge[(size_t)(e + stride) * 32 + l], v1);
        __stcs(&out_edge[(size_t)(e + 2 * stride) * 32 + l], v2);
        __stcs(&out_edge[(size_t)(e + 3 * stride) * 32 + l], v3);
    }
    for (; e < end; e += stride) {
        int k = __ldg(&ef[e]);
        __stcs(&out_edge[(size_t)e * 32 + l], g_lnedge[(k << 5) + l]);
    }
}

// ==================== K1: node dict tables (100) + eout [0, E_SPLIT) ====================
#define G1 1184
#define EO1_BLKS (G1 - ND)     // 1084

__global__ void __launch_bounds__(256) k1_nodetab(
    const float* __restrict__ node_emb,
    const float* __restrict__ W_t, const float* __restrict__ b_t,
    const float* __restrict__ a_w,
    const int* __restrict__ ef, float4* __restrict__ out_edge)
{
    int bid = blockIdx.x;
    int tid = threadIdx.x;

    if (bid >= ND) {
        int eb = bid - ND;
        int l = tid & 31;
        int gw = eb * 8 + (tid >> 5);
        eout_stream(ef, out_edge, 0, E_SPLIT, gw, l, EO1_BLKS * 8);
        return;
    }

    __shared__ float sh[128];
    __shared__ float part[128];
    int col = tid & 127;
    int half = tid >> 7;

    float acc = dict_gemv(node_emb + bid * 128, W_t, b_t, sh, part, col, half);
    if (half == 1) return;

    int h = col >> 5;
    int f = col & 31;
    ((float*)&g_tabT[bid * 32 + f])[h] = acc;
    float u = acc * a_w[f];
    float v = acc * a_w[32 + f];
#pragma unroll
    for (int o = 16; o; o >>= 1) {
        u += __shfl_xor_sync(0xFFFFFFFFu, u, o);
        v += __shfl_xor_sync(0xFFFFFFFFu, v, o);
    }
    if (f == 0) {
        ((float*)&g_s1[bid])[h] = u;
        ((float*)&g_s2[bid])[h] = v;
    }
}

// ==================== K2: edge atomics (all edges) + warp-fused eout [E_SPLIT, NE) ====================
// One lane per edge; 32 edges per warp (NE % 32 == 0 -> all chunks full).
#define NCH (NE / 32)               // 12500 chunks
#define G2 1563                     // 1563*8 = 12504 warps

__global__ void __launch_bounds__(256) k2_edges(
    const int* __restrict__ nf, const int* __restrict__ ef,
    const int* __restrict__ ei, const float* __restrict__ a_b,
    float4* __restrict__ out_edge)
{
    int tid = threadIdx.x;
    int l = tid & 31;
    int gw = blockIdx.x * 8 + (tid >> 5);
    if (gw >= NCH) return;
    int base = gw * 32;
    int e = base + l;

    // ---- per-lane edge logit + atomics ----
    int s  = __ldg(&ei[e]);
    int t  = __ldg(&ei[NE + e]);
    int k  = __ldg(&ef[e]);
    int ds = __ldg(&nf[s]);
    int dt = __ldg(&nf[t]);
    float ab = __ldg(a_b);
    float4 z1 = g_s1[dt];
    float4 z2 = g_s2[ds];
    float4 z3 = g_s3[k];

    float zx = z1.x + z2.x + z3.x + ab;
    float zy = z1.y + z2.y + z3.y + ab;
    float zz = z1.z + z2.z + z3.z + ab;
    float zw = z1.w + z2.w + z3.w + ab;
    zx = zx >= 0.f ? zx : 0.2f * zx;
    zy = zy >= 0.f ? zy : 0.2f * zy;
    zz = zz >= 0.f ? zz : 0.2f * zz;
    zw = zw >= 0.f ? zw : 0.2f * zw;
    float ex = __expf(zx), ey = __expf(zy), ez = __expf(zz), ew = __expf(zw);

    float4* wp = &g_Wmat[t * ND + ds];
    asm volatile("red.global.add.v4.f32 [%0], {%1,%2,%3,%4};"
                 :: "l"(wp), "f"(ex), "f"(ey), "f"(ez), "f"(ew) : "memory");
    atomicAdd(&g_deg[t], 1);

    // ---- warp-fused edge-out: broadcast k across lanes, coalesced 512B rows ----
    if (base >= E_SPLIT) {
        float4* orow = out_edge + (size_t)base * 32 + l;
#pragma unroll
        for (int j = 0; j < 32; j += 4) {
            int k0 = __shfl_sync(0xFFFFFFFFu, k, j);
            int k1 = __shfl_sync(0xFFFFFFFFu, k, j + 1);
            int k2 = __shfl_sync(0xFFFFFFFFu, k, j + 2);
            int k3 = __shfl_sync(0xFFFFFFFFu, k, j + 3);
            float4 v0 = g_lnedge[(k0 << 5) + l];
            float4 v1 = g_lnedge[(k1 << 5) + l];
            float4 v2 = g_lnedge[(k2 << 5) + l];
            float4 v3 = g_lnedge[(k3 << 5) + l];
            __stcs(orow + (size_t)(j + 0) * 32, v0);
            __stcs(orow + (size_t)(j + 1) * 32, v1);
            __stcs(orow + (size_t)(j + 2) * 32, v2);
            __stcs(orow + (size_t)(j + 3) * 32, v3);
        }
    }
}

// ==================== K3: node GEMM+LN+restore, one 16-node tile per block ====================
#define NPB3 16
#define NT3 ((NN + NPB3 - 1) / NPB3)   // 1563

__global__ void __launch_bounds__(256) k3_nodes(
    const int* __restrict__ nf,
    const float* __restrict__ gamma, const float* __restrict__ beta,
    float* __restrict__ out_node)
{
    __shared__ float4 Ws[NPB3 * ND];   // 25.6KB
    int tid = threadIdx.x;
    int l = tid & 31;
    int w = tid >> 5;
    int base = blockIdx.x * NPB3;
    const float4 z4 = make_float4(0.f, 0.f, 0.f, 0.f);

    for (int i = tid; i < NPB3 * ND; i += 256) {
        int t = base + i / ND;
        Ws[i] = (t < NN) ? __ldcs(&g_Wmat[t * ND + (i % ND)]) : z4;
    }
    __syncthreads();
    // restore zeros for the next graph replay (L2-resident batched stores)
    for (int i = tid; i < NPB3 * ND; i += 256) {
        int t = base + i / ND;
        if (t < NN) g_Wmat[t * ND + (i % ND)] = z4;
    }

    const float4* Wa = &Ws[(2 * w + 0) * ND];
    const float4* Wb = &Ws[(2 * w + 1) * ND];
    float4 acc0 = z4, acc1 = z4, ss0 = z4, ss1 = z4;

#pragma unroll 4
    for (int d = 0; d < ND; d++) {
        float4 wa = Wa[d], wb = Wb[d];
        if (wa.x + wb.x > 0.f) {
            float4 p = __ldg(&g_tabT[(d << 5) + l]);
            acc0.x += wa.x * p.x; acc0.y += wa.y * p.y; acc0.z += wa.z * p.z; acc0.w += wa.w * p.w;
            acc1.x += wb.x * p.x; acc1.y += wb.y * p.y; acc1.z += wb.z * p.z; acc1.w += wb.w * p.w;
            ss0.x += wa.x; ss0.y += wa.y; ss0.z += wa.z; ss0.w += wa.w;
            ss1.x += wb.x; ss1.y += wb.y; ss1.z += wb.z; ss1.w += wb.w;
        }
    }

    float gl0 = gamma[l],      bl0 = beta[l];
    float gl1 = gamma[32 + l], bl1 = beta[32 + l];
    float gl2 = gamma[64 + l], bl2 = beta[64 + l];
    float gl3 = gamma[96 + l], bl3 = beta[96 + l];

#pragma unroll
    for (int n = 0; n < 2; n++) {
        int t = base + 2 * w + n;
        if (t >= NN) break;
        float4 a  = (n == 0) ? acc0 : acc1;
        float4 ss = (n == 0) ? ss0  : ss1;
        float r0 = ss.x > 0.f ? 1.f / ss.x : 0.f;
        float r1 = ss.y > 0.f ? 1.f / ss.y : 0.f;
        float r2 = ss.z > 0.f ? 1.f / ss.z : 0.f;
        float r3 = ss.w > 0.f ? 1.f / ss.w : 0.f;
        float dg = (float)__ldg(&g_deg[t]);
        if (l == 0) g_deg[t] = 0;                       // restore
        float4 p = __ldg(&g_tabT[(__ldg(&nf[t]) << 5) + l]);

        float v0 = a.x * r0 + dg * p.x;
        float v1 = a.y * r1 + dg * p.y;
        float v2 = a.z * r2 + dg * p.z;
        float v3 = a.w * r3 + dg * p.w;

        float s = v0 + v1 + v2 + v3;
#pragma unroll
        for (int o = 16; o; o >>= 1) s += __shfl_xor_sync(0xFFFFFFFFu, s, o);
        float mu = s * (1.f / 128.f);
        float d0 = v0 - mu, d1 = v1 - mu, d2 = v2 - mu, d3 = v3 - mu;
        float sq = d0 * d0 + d1 * d1 + d2 * d2 + d3 * d3;
#pragma unroll
        for (int o = 16; o; o >>= 1) sq += __shfl_xor_sync(0xFFFFFFFFu, sq, o);
        float rs = rsqrtf(sq * (1.f / 128.f) + 1e-5f);

        float* o0 = out_node + (size_t)t * 128;
        __stcs(&o0[l],      d0 * rs * gl0 + bl0);
        __stcs(&o0[32 + l], d1 * rs * gl1 + bl1);
        __stcs(&o0[64 + l], d2 * rs * gl2 + bl2);
        __stcs(&o0[96 + l], d3 * rs * gl3 + bl3);
    }
}

// ==================== launch ====================
extern "C" void kernel_launch(void* const* d_in, const int* in_sizes, int n_in,
                              void* d_out, int out_size) {
    const int*   nf       = (const int*)d_in[0];
    const int*   ef       = (const int*)d_in[1];
    const int*   ei       = (const int*)d_in[2];
    const float* node_emb = (const float*)d_in[3];
    const float* edge_emb = (const float*)d_in[4];
    const float* W_t      = (const float*)d_in[5];
    const float* b_t      = (const float*)d_in[6];
    const float* W_e      = (const float*)d_in[7];
    const float* b_e      = (const float*)d_in[8];
    const float* a_w      = (const float*)d_in[9];
    const float* a_b      = (const float*)d_in[10];
    const float* gamma    = (const float*)d_in[11];
    const float* beta     = (const float*)d_in[12];

    float* out_node = (float*)d_out;                                  // [25000,128]
    float4* out_edge = (float4*)((float*)d_out + (size_t)NN * 128);   // [400000,128]

    k0_edgetab<<<EDICT, 256>>>(edge_emb, W_e, b_e, a_w, gamma, beta);
    k1_nodetab<<<G1, 256>>>(node_emb, W_t, b_t, a_w, ef, out_edge);
    k2_edges<<<G2, 256>>>(nf, ef, ei, a_b, out_edge);
    k3_nodes<<<NT3, 256>>>(nf, gamma, beta, out_node);
}